// round 16
// baseline (speedup 1.0000x reference)
#include <cuda_runtime.h>
#include <stdint.h>

// Problem constants
#define B_     16
#define N_     4096
#define TOTAL  (B_ * N_)      // 65536 tokens
#define DIM_   1024
#define E_     64
#define T_     8

#define BM 128
#define BKC 64
#define NCHUNK (DIM_ / BKC)    // 16
#define NTILES ((TOTAL / BM) + T_)   // 520
#define PERM_CAP (NTILES * BM)

// tf32 images: 272B rows (68 words), ldsm conflict-free, 16B aligned
#define XROW   272
#define XIMG   (BM * XROW)       // 34816 (single buffer)
#define WROW_WORDS 68
#define WIMG   (E_ * XROW)       // 17408 per stage
#define WCHUNK_WORDS (E_ * WROW_WORDS)   // 4352

#define OFF_X    0
#define OFF_W    34816
#define OFF_SROW 69632
#define SMEM_TOTAL 70144

#define CNT_BLOCKS 64
#define WTILE_BLOCKS (T_ * NCHUNK)       // 128 transpose tiles

// ---------------- device scratch ----------------
__device__ int g_partial[CNT_BLOCKS * T_];
__device__ int g_blockBase[CNT_BLOCKS * T_];
__device__ int g_counts[T_];
__device__ int g_paddedOff[T_ + 1];
__device__ int g_ticket;             // zero-init; self-resetting each launch
__device__ int g_perm[PERM_CAP];
__device__ __align__(16) uint32_t g_W[T_ * NCHUNK * WCHUNK_WORDS];  // pre-rounded tf32

// ---------------- helpers ----------------
__device__ __forceinline__ uint32_t smem_u32(const void* p) {
    uint32_t a;
    asm("{ .reg .u64 t; cvta.to.shared.u64 t, %1; cvt.u32.u64 %0, t; }" : "=r"(a) : "l"(p));
    return a;
}

__device__ __forceinline__ void ldsm4(uint32_t addr, uint32_t* r) {
    asm volatile("ldmatrix.sync.aligned.m8n8.x4.shared.b16 {%0,%1,%2,%3}, [%4];"
                 : "=r"(r[0]), "=r"(r[1]), "=r"(r[2]), "=r"(r[3]) : "r"(addr));
}

__device__ __forceinline__ void mma_tf32(float* c, const uint32_t* a,
                                         uint32_t b0, uint32_t b1) {
    asm volatile(
        "mma.sync.aligned.m16n8k8.row.col.f32.tf32.tf32.f32 "
        "{%0,%1,%2,%3}, {%4,%5,%6,%7}, {%8,%9}, {%0,%1,%2,%3};"
        : "+f"(c[0]), "+f"(c[1]), "+f"(c[2]), "+f"(c[3])
        : "r"(a[0]), "r"(a[1]), "r"(a[2]), "r"(a[3]), "r"(b0), "r"(b1));
}

__device__ __forceinline__ uint32_t to_tf32(float x) {
    uint32_t t;
    asm("cvt.rna.tf32.f32 %0, %1;" : "=r"(t) : "f"(x));
    return t;
}

__device__ __forceinline__ void cp_async16(uint32_t saddr, const void* gaddr) {
    asm volatile("cp.async.cg.shared.global [%0], [%1], 16;"
                 :: "r"(saddr), "l"(gaddr));
}
#define CP_COMMIT() asm volatile("cp.async.commit_group;" ::: "memory")
#define CP_WAIT0()  asm volatile("cp.async.wait_group 0;" ::: "memory")

// ---------------- kernel 1: count + fused last-block scan (64 blocks) ----------------
__global__ void count_scan_kernel(const int* __restrict__ idx) {
    __shared__ int cs[T_];
    if (threadIdx.x < T_) cs[threadIdx.x] = 0;
    __syncthreads();
    int i = blockIdx.x * 256 + threadIdx.x;
    int4 v = ((const int4*)idx)[i];
    int lane = threadIdx.x & 31;
#pragma unroll
    for (int q = 0; q < 4; q++) {
        int h = ((q == 0) ? v.x : (q == 1) ? v.y : (q == 2) ? v.z : v.w) & 7;
        unsigned mask = __match_any_sync(0xffffffffu, h);
        if ((__ffs(mask) - 1) == lane) atomicAdd(&cs[h], __popc(mask));
    }
    __syncthreads();
    if (threadIdx.x < T_)
        g_partial[blockIdx.x * T_ + threadIdx.x] = cs[threadIdx.x];

    // ticket: last block performs the scan
    __shared__ int is_last;
    __syncthreads();
    if (threadIdx.x == 0) {
        __threadfence();
        is_last = (atomicAdd(&g_ticket, 1) == CNT_BLOCKS - 1);
    }
    __syncthreads();
    if (is_last) {
        __threadfence();
        int wid = threadIdx.x >> 5;
        int lane2 = threadIdx.x & 31;
        if (wid < T_) {
            int p0 = g_partial[lane2 * T_ + wid];
            int p1 = g_partial[(lane2 + 32) * T_ + wid];
            int s0 = p0;
#pragma unroll
            for (int d = 1; d < 32; d <<= 1) {
                int v2 = __shfl_up_sync(0xffffffffu, s0, d);
                if (lane2 >= d) s0 += v2;
            }
            int tot0 = __shfl_sync(0xffffffffu, s0, 31);
            int s1 = p1;
#pragma unroll
            for (int d = 1; d < 32; d <<= 1) {
                int v2 = __shfl_up_sync(0xffffffffu, s1, d);
                if (lane2 >= d) s1 += v2;
            }
            g_blockBase[lane2 * T_ + wid] = s0 - p0;
            g_blockBase[(lane2 + 32) * T_ + wid] = tot0 + s1 - p1;
            if (lane2 == 31) g_counts[wid] = tot0 + s1;
        }
        __syncthreads();
        if (threadIdx.x == 0) {
            int off = 0;
            for (int hh = 0; hh < T_; hh++) {
                g_paddedOff[hh] = off;
                off += ((g_counts[hh] + BM - 1) / BM) * BM;
            }
            g_paddedOff[T_] = off;
            g_ticket = 0;   // reset for next launch (deterministic replays)
        }
    }
}

// ---------------- kernel 2: scatter (blocks 0..63) + wprep transpose (64..191) ----------------
__global__ void scatter_wprep_kernel(const int* __restrict__ idx,
                                     const float* __restrict__ W) {
    if (blockIdx.x < CNT_BLOCKS) {
        __shared__ int scnt[T_], sbase[T_];
        int t = threadIdx.x;
        int lane = t & 31;
        if (t < T_) scnt[t] = 0;
        __syncthreads();
        int i = blockIdx.x * 256 + t;
        int4 v = ((const int4*)idx)[i];
        int hq[4], rq[4];
#pragma unroll
        for (int q = 0; q < 4; q++) {
            int h = ((q == 0) ? v.x : (q == 1) ? v.y : (q == 2) ? v.z : v.w) & 7;
            unsigned mask = __match_any_sync(0xffffffffu, h);
            int leader = __ffs(mask) - 1;
            int rank = __popc(mask & ((1u << lane) - 1u));
            int base = 0;
            if (lane == leader) base = atomicAdd(&scnt[h], __popc(mask));
            base = __shfl_sync(0xffffffffu, base, leader);
            hq[q] = h;
            rq[q] = base + rank;
        }
        __syncthreads();
        if (t < T_) sbase[t] = g_paddedOff[t] + g_blockBase[blockIdx.x * T_ + t];
        __syncthreads();
#pragma unroll
        for (int q = 0; q < 4; q++)
            g_perm[sbase[hq[q]] + rq[q]] = i * 4 + q;
    } else {
        // ---- wprep: one 64(k) x 64(n) tile per block, smem transpose ----
        __shared__ float s[64][68];
        int tIdx = blockIdx.x - CNT_BLOCKS;
        int h = tIdx >> 4;
        int c = tIdx & 15;
        int t = threadIdx.x;
        const int col4 = t & 15;
        const int krow = t >> 4;

#pragma unroll
        for (int p = 0; p < 4; p++) {
            int k = p * 16 + krow;
            float4 v = *(const float4*)(W + ((size_t)h * DIM_ + c * 64 + k) * E_ + col4 * 4);
            s[k][col4 * 4 + 0] = v.x;
            s[k][col4 * 4 + 1] = v.y;
            s[k][col4 * 4 + 2] = v.z;
            s[k][col4 * 4 + 3] = v.w;
        }
        __syncthreads();

        uint32_t* dst = g_W + (size_t)tIdx * WCHUNK_WORDS;
        const int n = t >> 2;
#pragma unroll
        for (int p = 0; p < 4; p++) {
            int k = p * 16 + (t & 3) * 4;
            uint4 w = make_uint4(to_tf32(s[k][n]), to_tf32(s[k + 1][n]),
                                 to_tf32(s[k + 2][n]), to_tf32(s[k + 3][n]));
            *(uint4*)(dst + n * WROW_WORDS + k) = w;
        }
    }
}

// ---------------- tf32 GEMM: unchanged from measured 82.4us version ----------------
__global__ __launch_bounds__(256, 2)
void gemm_mma(const float* __restrict__ X,
              const float* __restrict__ bias,
              float* __restrict__ out)
{
    const int tileBase = blockIdx.x * BM;
    if (tileBase >= g_paddedOff[T_]) return;

    int head = 0;
    while (g_paddedOff[head + 1] <= tileBase) head++;

    extern __shared__ char sm[];
    const uint32_t sbase = smem_u32(sm);
    int* srow = (int*)(sm + OFF_SROW);

    const int tid = threadIdx.x;
    const int wid = tid >> 5;
    const int lane = tid & 31;
    const int wm = wid & 3;
    const int wn = wid >> 2;

    const int vcnt = g_counts[head] - (tileBase - g_paddedOff[head]);
    if (tid < BM) srow[tid] = (tid < vcnt) ? g_perm[tileBase + tid] : -1;
    __syncthreads();

    uint32_t aOff[2];
#pragma unroll
    for (int t = 0; t < 2; t++) {
        uint32_t r = 32 * wm + 16 * t + (lane & 7) + ((lane >> 3) & 1) * 8;
        aOff[t] = r * XROW + (lane >> 4) * 16;
    }
    uint32_t bOff[2];
#pragma unroll
    for (int p = 0; p < 2; p++) {
        uint32_t r = 32 * wn + 16 * p + ((lane >> 4) << 3) + (lane & 7);
        bOff[p] = r * XROW + ((lane >> 3) & 1) * 16;
    }

    // X stager: 16 threads per row at 16B granularity (conflict-free STS)
    const int j4 = tid & 15;
    const int rp = tid >> 4;
    int xtok[8];
#pragma unroll
    for (int p = 0; p < 8; p++) xtok[p] = srow[rp + 16 * p];

    const uint32_t wSrcBase = (uint32_t)(head * NCHUNK) * WCHUNK_WORDS;

    float acc[32];
#pragma unroll
    for (int i = 0; i < 32; i++) acc[i] = 0.0f;

    char* xb = sm + OFF_X;

    float4 pf[8];

    auto ldgX = [&](int c) {
        const int k0 = c * BKC + j4 * 4;
#pragma unroll
        for (int p = 0; p < 8; p++) {
            if (xtok[p] >= 0)
                pf[p] = *(const float4*)(X + (size_t)xtok[p] * DIM_ + k0);
            else
                pf[p] = make_float4(0.f, 0.f, 0.f, 0.f);
        }
    };
    auto cpW = [&](int c) {
        const uint32_t ws = wSrcBase + c * WCHUNK_WORDS;
        const uint4* src = (const uint4*)(g_W + ws);
        uint32_t wd = sbase + OFF_W + (c & 1) * WIMG;
        for (int i = tid; i < WCHUNK_WORDS / 4; i += 256)
            cp_async16(wd + i * 16, src + i);
        CP_COMMIT();
    };

    ldgX(0);
    cpW(0);

    for (int chunk = 0; chunk < NCHUNK; chunk++) {
#pragma unroll
        for (int p = 0; p < 8; p++) {
            float4 v = pf[p];
            uint4 w = make_uint4(to_tf32(v.x), to_tf32(v.y), to_tf32(v.z), to_tf32(v.w));
            uint32_t off = (uint32_t)((rp + 16 * p) * XROW + j4 * 16);
            *(uint4*)(xb + off) = w;
        }

        if (chunk + 1 < NCHUNK) ldgX(chunk + 1);

        CP_WAIT0();
        __syncthreads();

        if (chunk + 1 < NCHUNK) cpW(chunk + 1);

        const uint32_t wb = sbase + OFF_W + (chunk & 1) * WIMG;
#pragma unroll
        for (int ks = 0; ks < 8; ks++) {
            uint32_t a[2][4];
#pragma unroll
            for (int t = 0; t < 2; t++)
                ldsm4(sbase + OFF_X + aOff[t] + ks * 32, a[t]);
            uint32_t b[2][4];
#pragma unroll
            for (int p = 0; p < 2; p++)
                ldsm4(wb + bOff[p] + ks * 32, b[p]);
#pragma unroll
            for (int t = 0; t < 2; t++)
#pragma unroll
                for (int nb = 0; nb < 4; nb++)
                    mma_tf32(acc + (t * 4 + nb) * 4, a[t],
                             b[nb >> 1][(nb & 1) * 2], b[nb >> 1][(nb & 1) * 2 + 1]);
        }
        __syncthreads();
    }

    const float* bh = bias + head * E_;
    const int e0 = 2 * (lane & 3);
#pragma unroll
    for (int t = 0; t < 2; t++) {
        int r1 = 32 * wm + 16 * t + (lane >> 2);
        int tok1 = srow[r1];
        int tok2 = srow[r1 + 8];
#pragma unroll
        for (int q = 0; q < 4; q++) {
            int e = 32 * wn + 8 * q + e0;
            float be0 = bh[e], be1 = bh[e + 1];
            const float* a = acc + (t * 4 + q) * 4;
            if (tok1 >= 0)
                *(float2*)(out + (size_t)tok1 * E_ + e) = make_float2(a[0] + be0, a[1] + be1);
            if (tok2 >= 0)
                *(float2*)(out + (size_t)tok2 * E_ + e) = make_float2(a[2] + be0, a[3] + be1);
        }
    }
}

// ---------------- launch ----------------
extern "C" void kernel_launch(void* const* d_in, const int* in_sizes, int n_in,
                              void* d_out, int out_size)
{
    const float* X    = (const float*)d_in[0];
    const int*   idx  = (const int*)d_in[1];     // int32 (JAX demotes int64)
    const float* W    = (const float*)d_in[2];
    const float* bias = (const float*)d_in[3];
    float*       out  = (float*)d_out;

    static int attr_set = 0;
    if (!attr_set) {
        cudaFuncSetAttribute(gemm_mma, cudaFuncAttributeMaxDynamicSharedMemorySize, SMEM_TOTAL);
        attr_set = 1;
    }

    count_scan_kernel<<<CNT_BLOCKS, 256>>>(idx);
    scatter_wprep_kernel<<<CNT_BLOCKS + WTILE_BLOCKS, 256>>>(idx, W);
    gemm_mma<<<NTILES, 256, SMEM_TOTAL>>>(X, bias, out);
}

// round 17
// speedup vs baseline: 1.0082x; 1.0082x over previous
#include <cuda_runtime.h>
#include <stdint.h>

// Problem constants
#define B_     16
#define N_     4096
#define TOTAL  (B_ * N_)      // 65536 tokens
#define DIM_   1024
#define E_     64
#define T_     8

#define BM 128
#define BKC 64
#define NCHUNK (DIM_ / BKC)    // 16
#define NTILES ((TOTAL / BM) + T_)   // 520
#define PERM_CAP (NTILES * BM)

// tf32 images: 272B rows (68 words), ldsm conflict-free, 16B aligned
#define XROW   272
#define XIMG   (BM * XROW)       // 34816 (single buffer)
#define WROW_WORDS 68
#define WIMG   (E_ * XROW)       // 17408 per stage
#define WCHUNK_WORDS (E_ * WROW_WORDS)   // 4352

#define OFF_X    0
#define OFF_W    34816
#define OFF_SROW 69632
#define SMEM_TOTAL 70144

#define CNT_BLOCKS 64
#define WTILE_BLOCKS (T_ * NCHUNK)       // 128 transpose tiles
#define AUX_BLOCKS (CNT_BLOCKS + WTILE_BLOCKS)

// ---------------- device scratch ----------------
__device__ int g_partial[CNT_BLOCKS * T_];
__device__ int g_blockBase[CNT_BLOCKS * T_];
__device__ int g_counts[T_];
__device__ int g_paddedOff[T_ + 1];
__device__ int g_ticket;             // zero-init; self-resetting
__device__ volatile int g_flag;      // scan-done flag; self-resetting
__device__ int g_done;               // completion counter; self-resetting
__device__ int g_perm[PERM_CAP];
__device__ __align__(16) uint32_t g_W[T_ * NCHUNK * WCHUNK_WORDS];  // pre-rounded tf32

// ---------------- helpers ----------------
__device__ __forceinline__ uint32_t smem_u32(const void* p) {
    uint32_t a;
    asm("{ .reg .u64 t; cvta.to.shared.u64 t, %1; cvt.u32.u64 %0, t; }" : "=r"(a) : "l"(p));
    return a;
}

__device__ __forceinline__ void ldsm4(uint32_t addr, uint32_t* r) {
    asm volatile("ldmatrix.sync.aligned.m8n8.x4.shared.b16 {%0,%1,%2,%3}, [%4];"
                 : "=r"(r[0]), "=r"(r[1]), "=r"(r[2]), "=r"(r[3]) : "r"(addr));
}

__device__ __forceinline__ void mma_tf32(float* c, const uint32_t* a,
                                         uint32_t b0, uint32_t b1) {
    asm volatile(
        "mma.sync.aligned.m16n8k8.row.col.f32.tf32.tf32.f32 "
        "{%0,%1,%2,%3}, {%4,%5,%6,%7}, {%8,%9}, {%0,%1,%2,%3};"
        : "+f"(c[0]), "+f"(c[1]), "+f"(c[2]), "+f"(c[3])
        : "r"(a[0]), "r"(a[1]), "r"(a[2]), "r"(a[3]), "r"(b0), "r"(b1));
}

__device__ __forceinline__ uint32_t to_tf32(float x) {
    uint32_t t;
    asm("cvt.rna.tf32.f32 %0, %1;" : "=r"(t) : "f"(x));
    return t;
}

__device__ __forceinline__ void cp_async16(uint32_t saddr, const void* gaddr) {
    asm volatile("cp.async.cg.shared.global [%0], [%1], 16;"
                 :: "r"(saddr), "l"(gaddr));
}
#define CP_COMMIT() asm volatile("cp.async.commit_group;" ::: "memory")
#define CP_WAIT0()  asm volatile("cp.async.wait_group 0;" ::: "memory")

// ---------------- fused aux: count+scan+scatter (blocks 0..63) | wprep (64..191) --------
__global__ void aux_kernel(const int* __restrict__ idx, const float* __restrict__ W) {
    if (blockIdx.x < CNT_BLOCKS) {
        __shared__ int scnt[T_], sbase[T_];
        int t = threadIdx.x;
        int lane = t & 31;
        if (t < T_) scnt[t] = 0;
        __syncthreads();

        // ---- single idx read; compute head + block-local rank per token ----
        int i = blockIdx.x * 256 + t;
        int4 v = ((const int4*)idx)[i];
        int hq[4], rq[4];
#pragma unroll
        for (int q = 0; q < 4; q++) {
            int h = ((q == 0) ? v.x : (q == 1) ? v.y : (q == 2) ? v.z : v.w) & 7;
            unsigned mask = __match_any_sync(0xffffffffu, h);
            int leader = __ffs(mask) - 1;
            int rank = __popc(mask & ((1u << lane) - 1u));
            int base = 0;
            if (lane == leader) base = atomicAdd(&scnt[h], __popc(mask));
            base = __shfl_sync(0xffffffffu, base, leader);
            hq[q] = h;
            rq[q] = base + rank;
        }
        __syncthreads();
        if (t < T_)
            g_partial[blockIdx.x * T_ + t] = scnt[t];

        // ---- ticket: last counting block scans + releases flag ----
        __shared__ int is_last;
        __syncthreads();
        if (t == 0) {
            __threadfence();
            is_last = (atomicAdd(&g_ticket, 1) == CNT_BLOCKS - 1);
        }
        __syncthreads();
        if (is_last) {
            __threadfence();
            int wid = t >> 5;
            int lane2 = t & 31;
            if (wid < T_) {
                int p0 = g_partial[lane2 * T_ + wid];
                int p1 = g_partial[(lane2 + 32) * T_ + wid];
                int s0 = p0;
#pragma unroll
                for (int d = 1; d < 32; d <<= 1) {
                    int v2 = __shfl_up_sync(0xffffffffu, s0, d);
                    if (lane2 >= d) s0 += v2;
                }
                int tot0 = __shfl_sync(0xffffffffu, s0, 31);
                int s1 = p1;
#pragma unroll
                for (int d = 1; d < 32; d <<= 1) {
                    int v2 = __shfl_up_sync(0xffffffffu, s1, d);
                    if (lane2 >= d) s1 += v2;
                }
                g_blockBase[lane2 * T_ + wid] = s0 - p0;
                g_blockBase[(lane2 + 32) * T_ + wid] = tot0 + s1 - p1;
                if (lane2 == 31) g_counts[wid] = tot0 + s1;
            }
            __syncthreads();
            if (t == 0) {
                int off = 0;
                for (int hh = 0; hh < T_; hh++) {
                    g_paddedOff[hh] = off;
                    off += ((g_counts[hh] + BM - 1) / BM) * BM;
                }
                g_paddedOff[T_] = off;
                __threadfence();
                g_flag = 1;          // release
            }
        }

        // ---- all counting blocks spin until scan done (co-resident: 64 < 148) ----
        if (t == 0) {
            while (g_flag == 0)
                __nanosleep(64);
        }
        __syncthreads();
        __threadfence();             // acquire

        // ---- scatter using retained ranks ----
        if (t < T_) sbase[t] = g_paddedOff[t] + g_blockBase[blockIdx.x * T_ + t];
        __syncthreads();
#pragma unroll
        for (int q = 0; q < 4; q++)
            g_perm[sbase[hq[q]] + rq[q]] = i * 4 + q;

        // ---- self-reset for deterministic graph replays ----
        __syncthreads();
        if (t == 0) {
            __threadfence();
            if (atomicAdd(&g_done, 1) == CNT_BLOCKS - 1) {
                g_ticket = 0;
                g_done = 0;
                g_flag = 0;
            }
        }
    } else {
        // ---- wprep: one 64(k) x 64(n) tile per block, smem transpose ----
        __shared__ float s[64][68];
        int tIdx = blockIdx.x - CNT_BLOCKS;
        int h = tIdx >> 4;
        int c = tIdx & 15;
        int t = threadIdx.x;
        const int col4 = t & 15;
        const int krow = t >> 4;

#pragma unroll
        for (int p = 0; p < 4; p++) {
            int k = p * 16 + krow;
            float4 v = *(const float4*)(W + ((size_t)h * DIM_ + c * 64 + k) * E_ + col4 * 4);
            s[k][col4 * 4 + 0] = v.x;
            s[k][col4 * 4 + 1] = v.y;
            s[k][col4 * 4 + 2] = v.z;
            s[k][col4 * 4 + 3] = v.w;
        }
        __syncthreads();

        uint32_t* dst = g_W + (size_t)tIdx * WCHUNK_WORDS;
        const int n = t >> 2;
#pragma unroll
        for (int p = 0; p < 4; p++) {
            int k = p * 16 + (t & 3) * 4;
            uint4 w = make_uint4(to_tf32(s[k][n]), to_tf32(s[k + 1][n]),
                                 to_tf32(s[k + 2][n]), to_tf32(s[k + 3][n]));
            *(uint4*)(dst + n * WROW_WORDS + k) = w;
        }
    }
}

// ---------------- tf32 GEMM: unchanged from measured 82.4us version ----------------
__global__ __launch_bounds__(256, 2)
void gemm_mma(const float* __restrict__ X,
              const float* __restrict__ bias,
              float* __restrict__ out)
{
    const int tileBase = blockIdx.x * BM;
    if (tileBase >= g_paddedOff[T_]) return;

    int head = 0;
    while (g_paddedOff[head + 1] <= tileBase) head++;

    extern __shared__ char sm[];
    const uint32_t sbase = smem_u32(sm);
    int* srow = (int*)(sm + OFF_SROW);

    const int tid = threadIdx.x;
    const int wid = tid >> 5;
    const int lane = tid & 31;
    const int wm = wid & 3;
    const int wn = wid >> 2;

    const int vcnt = g_counts[head] - (tileBase - g_paddedOff[head]);
    if (tid < BM) srow[tid] = (tid < vcnt) ? g_perm[tileBase + tid] : -1;
    __syncthreads();

    uint32_t aOff[2];
#pragma unroll
    for (int t = 0; t < 2; t++) {
        uint32_t r = 32 * wm + 16 * t + (lane & 7) + ((lane >> 3) & 1) * 8;
        aOff[t] = r * XROW + (lane >> 4) * 16;
    }
    uint32_t bOff[2];
#pragma unroll
    for (int p = 0; p < 2; p++) {
        uint32_t r = 32 * wn + 16 * p + ((lane >> 4) << 3) + (lane & 7);
        bOff[p] = r * XROW + ((lane >> 3) & 1) * 16;
    }

    // X stager: 16 threads per row at 16B granularity (conflict-free STS)
    const int j4 = tid & 15;
    const int rp = tid >> 4;
    int xtok[8];
#pragma unroll
    for (int p = 0; p < 8; p++) xtok[p] = srow[rp + 16 * p];

    const uint32_t wSrcBase = (uint32_t)(head * NCHUNK) * WCHUNK_WORDS;

    float acc[32];
#pragma unroll
    for (int i = 0; i < 32; i++) acc[i] = 0.0f;

    char* xb = sm + OFF_X;

    float4 pf[8];

    auto ldgX = [&](int c) {
        const int k0 = c * BKC + j4 * 4;
#pragma unroll
        for (int p = 0; p < 8; p++) {
            if (xtok[p] >= 0)
                pf[p] = *(const float4*)(X + (size_t)xtok[p] * DIM_ + k0);
            else
                pf[p] = make_float4(0.f, 0.f, 0.f, 0.f);
        }
    };
    auto cpW = [&](int c) {
        const uint32_t ws = wSrcBase + c * WCHUNK_WORDS;
        const uint4* src = (const uint4*)(g_W + ws);
        uint32_t wd = sbase + OFF_W + (c & 1) * WIMG;
        for (int i = tid; i < WCHUNK_WORDS / 4; i += 256)
            cp_async16(wd + i * 16, src + i);
        CP_COMMIT();
    };

    ldgX(0);
    cpW(0);

    for (int chunk = 0; chunk < NCHUNK; chunk++) {
#pragma unroll
        for (int p = 0; p < 8; p++) {
            float4 v = pf[p];
            uint4 w = make_uint4(to_tf32(v.x), to_tf32(v.y), to_tf32(v.z), to_tf32(v.w));
            uint32_t off = (uint32_t)((rp + 16 * p) * XROW + j4 * 16);
            *(uint4*)(xb + off) = w;
        }

        if (chunk + 1 < NCHUNK) ldgX(chunk + 1);

        CP_WAIT0();
        __syncthreads();

        if (chunk + 1 < NCHUNK) cpW(chunk + 1);

        const uint32_t wb = sbase + OFF_W + (chunk & 1) * WIMG;
#pragma unroll
        for (int ks = 0; ks < 8; ks++) {
            uint32_t a[2][4];
#pragma unroll
            for (int t = 0; t < 2; t++)
                ldsm4(sbase + OFF_X + aOff[t] + ks * 32, a[t]);
            uint32_t b[2][4];
#pragma unroll
            for (int p = 0; p < 2; p++)
                ldsm4(wb + bOff[p] + ks * 32, b[p]);
#pragma unroll
            for (int t = 0; t < 2; t++)
#pragma unroll
                for (int nb = 0; nb < 4; nb++)
                    mma_tf32(acc + (t * 4 + nb) * 4, a[t],
                             b[nb >> 1][(nb & 1) * 2], b[nb >> 1][(nb & 1) * 2 + 1]);
        }
        __syncthreads();
    }

    const float* bh = bias + head * E_;
    const int e0 = 2 * (lane & 3);
#pragma unroll
    for (int t = 0; t < 2; t++) {
        int r1 = 32 * wm + 16 * t + (lane >> 2);
        int tok1 = srow[r1];
        int tok2 = srow[r1 + 8];
#pragma unroll
        for (int q = 0; q < 4; q++) {
            int e = 32 * wn + 8 * q + e0;
            float be0 = bh[e], be1 = bh[e + 1];
            const float* a = acc + (t * 4 + q) * 4;
            if (tok1 >= 0)
                *(float2*)(out + (size_t)tok1 * E_ + e) = make_float2(a[0] + be0, a[1] + be1);
            if (tok2 >= 0)
                *(float2*)(out + (size_t)tok2 * E_ + e) = make_float2(a[2] + be0, a[3] + be1);
        }
    }
}

// ---------------- launch ----------------
extern "C" void kernel_launch(void* const* d_in, const int* in_sizes, int n_in,
                              void* d_out, int out_size)
{
    const float* X    = (const float*)d_in[0];
    const int*   idx  = (const int*)d_in[1];     // int32 (JAX demotes int64)
    const float* W    = (const float*)d_in[2];
    const float* bias = (const float*)d_in[3];
    float*       out  = (float*)d_out;

    static int attr_set = 0;
    if (!attr_set) {
        cudaFuncSetAttribute(gemm_mma, cudaFuncAttributeMaxDynamicSharedMemorySize, SMEM_TOTAL);
        attr_set = 1;
    }

    aux_kernel<<<AUX_BLOCKS, 256>>>(idx, W);
    gemm_mma<<<NTILES, 256, SMEM_TOTAL>>>(X, bias, out);
}